// round 8
// baseline (speedup 1.0000x reference)
#include <cuda_runtime.h>
#include <math.h>
#include <stdint.h>

#define N_    32
#define C_    512
#define HW_   4096         // 64*64
#define D_    4
#define BLK_  128          // C_/D_
#define HID_  32           // C_/16
#define CD_   (C_ * D_)    // 2048
#define NPOOL (N_ * C_)    // 16384 pool rows
#define NGATH (N_ * C_)    // 16384 gather rows
#define NMLP  (N_ * D_)    // 128 mlp+rank tasks
#define GRID_ 592          // 148 SMs * 4 blocks — guaranteed co-resident
#define TPB_  256

// ---- scratch (no allocations allowed) ----
__device__ float g_avgp[N_ * C_];
__device__ float g_maxp[N_ * C_];
__device__ int   g_idx [N_ * C_];     // selected channels, output order
__device__ int   g_pool_ticket;
__device__ int   g_gath_ticket;
__device__ int   g_done[N_];          // pooled-row count per sample
__device__ int   g_rank_done[NMLP];   // per-(n,d) rank completion flag

// Reset all queue/flag state each launch (graph replays reuse device state).
__global__ void reset_kernel() {
    const int t = threadIdx.x;
    if (t == 0) { g_pool_ticket = 0; g_gath_ticket = 0; }
    if (t < N_)   g_done[t] = 0;
    if (t < NMLP) g_rank_done[t] = 0;
}

struct SmemPool { float ss[8]; float sm[8]; };
struct SmemMlp {
    float avg_s[C_], max_s[C_];
    float part_a[8 * HID_], part_m[8 * HID_];
    float hs[HID_];
    unsigned long long keys[C_];
};
union Smem { SmemPool p; SmemMlp m; };

__global__ __launch_bounds__(TPB_, 4) void fused_kernel(
    const float* __restrict__ x,
    const float* __restrict__ W1, const float* __restrict__ b1,
    const float* __restrict__ W2, const float* __restrict__ b2,
    float* __restrict__ out)
{
    __shared__ Smem sm;
    __shared__ int s_ticket;
    const int tid = threadIdx.x;
    const int bid = blockIdx.x;

    if (bid < NMLP) {
        // ============== MLP + sigmoid + top-128 rank for task bid ==========
        const int n = bid >> 2, d = bid & 3;
        if (tid == 0)
            while (((volatile int*)g_done)[n] < C_) __nanosleep(128);
        __syncthreads();
        __threadfence();

        sm.m.avg_s[tid]       = g_avgp[n * C_ + tid];
        sm.m.avg_s[tid + 256] = g_avgp[n * C_ + tid + 256];
        sm.m.max_s[tid]       = g_maxp[n * C_ + tid];
        sm.m.max_s[tid + 256] = g_maxp[n * C_ + tid + 256];
        __syncthreads();

        // Layer 1 (coalesced): warp w handles c = w, w+8, ...; lane j = hidden idx.
        {
            const int w = tid >> 5, j = tid & 31;
            float sa = 0.0f, smx = 0.0f;
            #pragma unroll 8
            for (int c = w; c < C_; c += 8) {
                float w1 = W1[c * HID_ + j];
                sa  = fmaf(sm.m.avg_s[c], w1, sa);
                smx = fmaf(sm.m.max_s[c], w1, smx);
            }
            sm.m.part_a[w * HID_ + j] = sa;
            sm.m.part_m[w * HID_ + j] = smx;
        }
        __syncthreads();
        if (tid < HID_) {
            float sa = 0.0f, smx = 0.0f;
            #pragma unroll
            for (int w = 0; w < 8; w++) {
                sa  += sm.m.part_a[w * HID_ + tid];
                smx += sm.m.part_m[w * HID_ + tid];
            }
            float bb = b1[tid];
            sm.m.hs[tid] = fmaxf(sa + bb, 0.0f) + fmaxf(smx + bb, 0.0f);
        }
        __syncthreads();

        // Layer 2 + sigmoid + sortable keys: 2 channels per thread.
        // key = (bits(sigmoid)<<16) | (65535-c): sigmoid>0 so float bits are
        // monotone; lower-index tiebreak in low bits = exact lax.top_k order.
        #pragma unroll
        for (int h = 0; h < 2; h++) {
            const int c = tid + h * 256;
            const int o = c * D_ + d;
            float acc = 2.0f * b2[o];
            #pragma unroll
            for (int k = 0; k < HID_; k++)
                acc = fmaf(sm.m.hs[k], W2[k * CD_ + o], acc);
            float v = 1.0f / (1.0f + expf(-acc));
            sm.m.keys[c] = ((unsigned long long)__float_as_uint(v) << 16) |
                           (unsigned long long)(65535 - c);
        }
        __syncthreads();

        // Rank-by-count for both channels in one sweep.
        {
            const unsigned long long k1 = sm.m.keys[tid];
            const unsigned long long k2 = sm.m.keys[tid + 256];
            int r1 = 0, r2 = 0;
            const ulonglong2* kk = reinterpret_cast<const ulonglong2*>(sm.m.keys);
            #pragma unroll 8
            for (int i = 0; i < C_ / 2; i++) {
                ulonglong2 u = kk[i];
                r1 += (u.x > k1) + (u.y > k1);
                r2 += (u.x > k2) + (u.y > k2);
            }
            if (r1 < BLK_) g_idx[n * C_ + d * BLK_ + r1] = tid;
            if (r2 < BLK_) g_idx[n * C_ + d * BLK_ + r2] = tid + 256;
        }
        __threadfence();
        __syncthreads();
        if (tid == 0) ((volatile int*)g_rank_done)[bid] = 1;
    } else {
        // ============== pool worker: drain row tickets =====================
        for (;;) {
            if (tid == 0) s_ticket = atomicAdd(&g_pool_ticket, 1);
            __syncthreads();
            const int row = s_ticket;
            __syncthreads();
            if (row >= NPOOL) break;

            const float4* xr = reinterpret_cast<const float4*>(x + (size_t)row * HW_);
            float s = 0.0f, m = -INFINITY;
            #pragma unroll
            for (int h = 0; h < 4; h++) {
                float4 v = xr[tid + h * 256];
                s += (v.x + v.y) + (v.z + v.w);
                m = fmaxf(m, fmaxf(fmaxf(v.x, v.y), fmaxf(v.z, v.w)));
            }
            #pragma unroll
            for (int off = 16; off > 0; off >>= 1) {
                s += __shfl_xor_sync(0xffffffffu, s, off);
                m = fmaxf(m, __shfl_xor_sync(0xffffffffu, m, off));
            }
            const int w = tid >> 5, l = tid & 31;
            if (l == 0) { sm.p.ss[w] = s; sm.p.sm[w] = m; }
            __syncthreads();
            if (tid == 0) {
                float ts = sm.p.ss[0], tm = sm.p.sm[0];
                #pragma unroll
                for (int ww = 1; ww < 8; ww++) {
                    ts += sm.p.ss[ww];
                    tm = fmaxf(tm, sm.p.sm[ww]);
                }
                g_avgp[row] = ts * (1.0f / HW_);
                g_maxp[row] = tm;
                __threadfence();
                atomicAdd(&g_done[row >> 9], 1);
            }
        }
    }

    // ============== gather: all blocks drain row tickets ===================
    for (;;) {
        if (tid == 0) s_ticket = atomicAdd(&g_gath_ticket, 1);
        __syncthreads();
        const int row = s_ticket;
        __syncthreads();
        if (row >= NGATH) break;

        if (tid == 0)
            while (((volatile int*)g_rank_done)[row >> 7] == 0) __nanosleep(128);
        __syncthreads();
        __threadfence();

        const int n = row >> 9;
        const int c = g_idx[row];
        const float4* src = reinterpret_cast<const float4*>(
            x + ((size_t)n * C_ + c) * HW_);
        float4* dst = reinterpret_cast<float4*>(out + (size_t)row * HW_);
        #pragma unroll
        for (int h = 0; h < 4; h++) {
            float4 v = __ldcs(src + tid + h * 256);
            __stcs(dst + tid + h * 256, v);
        }
    }
}

extern "C" void kernel_launch(void* const* d_in, const int* in_sizes, int n_in,
                              void* d_out, int out_size) {
    const float* x  = (const float*)d_in[0];
    const float* W1 = (const float*)d_in[1];
    const float* b1 = (const float*)d_in[2];
    const float* W2 = (const float*)d_in[3];
    const float* b2 = (const float*)d_in[4];
    float* out = (float*)d_out;

    reset_kernel<<<1, 256>>>();
    fused_kernel<<<GRID_, TPB_>>>(x, W1, b1, W2, b2, out);
}

// round 9
// speedup vs baseline: 1.2552x; 1.2552x over previous
#include <cuda_runtime.h>
#include <math.h>
#include <stdint.h>

#define N_    32
#define C_    512
#define HW_   4096         // 64*64
#define D_    4
#define BLK_  128          // C_/D_
#define HID_  32           // C_/16
#define CD_   (C_ * D_)    // 2048
#define NPOOL (N_ * C_)    // 16384 pool rows
#define NGATH (N_ * C_)    // 16384 gather rows
#define NMLP  (N_ * D_)    // 128 mlp+rank tasks
#define GRID_ 592          // 148 SMs * 4 blocks
#define TPB_  256

// ---- scratch (no allocations allowed) ----
__device__ float g_avgp[N_ * C_];
__device__ float g_maxp[N_ * C_];
__device__ int   g_idx [N_ * C_];     // selected channels, output order
__device__ int   g_pool_ticket;
__device__ int   g_gath_ticket;
__device__ int   g_done[N_];          // pooled-row count per sample
__device__ int   g_rank_done[NMLP];   // per-(n,d) rank completion flag

__global__ void reset_kernel() {
    const int t = threadIdx.x;
    if (t == 0) { g_pool_ticket = 0; g_gath_ticket = 0; }
    if (t < N_)   g_done[t] = 0;
    if (t < NMLP) g_rank_done[t] = 0;
}

struct SmemMlp {
    float avg_s[C_], max_s[C_];
    float part_a[8 * HID_], part_m[8 * HID_];
    float hs[HID_];
    unsigned long long keys[C_];
};

__global__ __launch_bounds__(TPB_, 4) void fused_kernel(
    const float* __restrict__ x,
    const float* __restrict__ W1, const float* __restrict__ b1,
    const float* __restrict__ W2, const float* __restrict__ b2,
    float* __restrict__ out)
{
    __shared__ SmemMlp sm;
    const int tid  = threadIdx.x;
    const int bid  = blockIdx.x;
    const int lane = tid & 31;

    if (bid < NMLP) {
        // ===== block-level MLP + sigmoid + top-128 rank for task bid =======
        const int n = bid >> 2, d = bid & 3;
        if (tid == 0)
            while (((volatile int*)g_done)[n] < C_) __nanosleep(128);
        __syncthreads();
        __threadfence();

        sm.avg_s[tid]       = g_avgp[n * C_ + tid];
        sm.avg_s[tid + 256] = g_avgp[n * C_ + tid + 256];
        sm.max_s[tid]       = g_maxp[n * C_ + tid];
        sm.max_s[tid + 256] = g_maxp[n * C_ + tid + 256];
        __syncthreads();

        // Layer 1 (coalesced): warp w -> channels c = w, w+8, ...; lane = hidden idx.
        {
            const int w = tid >> 5;
            float sa = 0.0f, smx = 0.0f;
            #pragma unroll 8
            for (int c = w; c < C_; c += 8) {
                float w1 = W1[c * HID_ + lane];
                sa  = fmaf(sm.avg_s[c], w1, sa);
                smx = fmaf(sm.max_s[c], w1, smx);
            }
            sm.part_a[w * HID_ + lane] = sa;
            sm.part_m[w * HID_ + lane] = smx;
        }
        __syncthreads();
        if (tid < HID_) {
            float sa = 0.0f, smx = 0.0f;
            #pragma unroll
            for (int w = 0; w < 8; w++) {
                sa  += sm.part_a[w * HID_ + tid];
                smx += sm.part_m[w * HID_ + tid];
            }
            float bb = b1[tid];
            sm.hs[tid] = fmaxf(sa + bb, 0.0f) + fmaxf(smx + bb, 0.0f);
        }
        __syncthreads();

        // Layer 2 + sigmoid + sortable keys (2 channels/thread).
        // key = (bits(sigmoid)<<16) | (65535-c): sigmoid>0 -> monotone bits;
        // low-bits index tiebreak = exact lax.top_k order.
        #pragma unroll
        for (int h = 0; h < 2; h++) {
            const int c = tid + h * 256;
            const int o = c * D_ + d;
            float acc = 2.0f * b2[o];
            #pragma unroll
            for (int k = 0; k < HID_; k++)
                acc = fmaf(sm.hs[k], W2[k * CD_ + o], acc);
            float v = 1.0f / (1.0f + expf(-acc));
            sm.keys[c] = ((unsigned long long)__float_as_uint(v) << 16) |
                         (unsigned long long)(65535 - c);
        }
        __syncthreads();

        {
            const unsigned long long k1 = sm.keys[tid];
            const unsigned long long k2 = sm.keys[tid + 256];
            int r1 = 0, r2 = 0;
            const ulonglong2* kk = reinterpret_cast<const ulonglong2*>(sm.keys);
            #pragma unroll 8
            for (int i = 0; i < C_ / 2; i++) {
                ulonglong2 u = kk[i];
                r1 += (u.x > k1) + (u.y > k1);
                r2 += (u.x > k2) + (u.y > k2);
            }
            if (r1 < BLK_) g_idx[n * C_ + d * BLK_ + r1] = tid;
            if (r2 < BLK_) g_idx[n * C_ + d * BLK_ + r2] = tid + 256;
        }
        __threadfence();
        __syncthreads();
        if (tid == 0) ((volatile int*)g_rank_done)[bid] = 1;
    } else {
        // ===== pool: warp-granular tickets, no block barriers ==============
        for (;;) {
            int row;
            if (lane == 0) row = atomicAdd(&g_pool_ticket, 1);
            row = __shfl_sync(0xffffffffu, row, 0);
            if (row >= NPOOL) break;

            const float4* xr = reinterpret_cast<const float4*>(x + (size_t)row * HW_);
            float s = 0.0f, m = -INFINITY;
            #pragma unroll 8
            for (int i = 0; i < 32; i++) {
                float4 v = xr[lane + i * 32];
                s += (v.x + v.y) + (v.z + v.w);
                m = fmaxf(m, fmaxf(fmaxf(v.x, v.y), fmaxf(v.z, v.w)));
            }
            #pragma unroll
            for (int off = 16; off > 0; off >>= 1) {
                s += __shfl_xor_sync(0xffffffffu, s, off);
                m = fmaxf(m, __shfl_xor_sync(0xffffffffu, m, off));
            }
            if (lane == 0) {
                g_avgp[row] = s * (1.0f / HW_);
                g_maxp[row] = m;
                __threadfence();
                atomicAdd(&g_done[row >> 9], 1);
            }
        }
    }

    // ===== gather: warp-granular tickets, all blocks ======================
    for (;;) {
        int row;
        if (lane == 0) row = atomicAdd(&g_gath_ticket, 1);
        row = __shfl_sync(0xffffffffu, row, 0);
        if (row >= NGATH) break;

        const int f = row >> 7;        // (n,d) flag index
        while (((volatile int*)g_rank_done)[f] == 0) __nanosleep(128);
        __threadfence();

        const int n = row >> 9;
        const int c = g_idx[row];
        const float4* src = reinterpret_cast<const float4*>(
            x + ((size_t)n * C_ + c) * HW_);
        float4* dst = reinterpret_cast<float4*>(out + (size_t)row * HW_);
        #pragma unroll 8
        for (int i = 0; i < 32; i++) {
            float4 v = __ldcs(src + lane + i * 32);
            __stcs(dst + lane + i * 32, v);
        }
    }
}

extern "C" void kernel_launch(void* const* d_in, const int* in_sizes, int n_in,
                              void* d_out, int out_size) {
    const float* x  = (const float*)d_in[0];
    const float* W1 = (const float*)d_in[1];
    const float* b1 = (const float*)d_in[2];
    const float* W2 = (const float*)d_in[3];
    const float* b2 = (const float*)d_in[4];
    float* out = (float*)d_out;

    reset_kernel<<<1, 256>>>();
    fused_kernel<<<GRID_, TPB_>>>(x, W1, b1, W2, b2, out);
}

// round 12
// speedup vs baseline: 1.4006x; 1.1159x over previous
#include <cuda_runtime.h>
#include <math.h>
#include <stdint.h>

#define N_   32
#define C_   512
#define HW_  4096          // 64*64
#define D_   4
#define BLK_ 128           // C_/D_
#define HID_ 32            // C_/16
#define CD_  (C_ * D_)     // 2048

// ---- scratch (no allocations allowed) ----
__device__ float g_avgp[N_ * C_];
__device__ float g_maxp[N_ * C_];
__device__ int   g_idx [N_ * C_];   // selected channels, output order

// ---------------------------------------------------------------------------
// K1: per-(n,c) avg + max pooling. One block per row. (At DRAM roofline.)
// ---------------------------------------------------------------------------
__global__ __launch_bounds__(256) void pool_kernel(const float* __restrict__ x) {
    const int row = blockIdx.x;                      // n*C + c
    const float4* xr = reinterpret_cast<const float4*>(x + (size_t)row * HW_);

    float s = 0.0f;
    float m = -INFINITY;
    #pragma unroll 4
    for (int i = threadIdx.x; i < HW_ / 4; i += 256) {
        float4 v = xr[i];
        s += (v.x + v.y) + (v.z + v.w);
        m = fmaxf(m, fmaxf(fmaxf(v.x, v.y), fmaxf(v.z, v.w)));
    }
    #pragma unroll
    for (int off = 16; off > 0; off >>= 1) {
        s += __shfl_xor_sync(0xffffffffu, s, off);
        m = fmaxf(m, __shfl_xor_sync(0xffffffffu, m, off));
    }
    __shared__ float ss[8], sm[8];
    const int wid = threadIdx.x >> 5;
    const int lid = threadIdx.x & 31;
    if (lid == 0) { ss[wid] = s; sm[wid] = m; }
    __syncthreads();
    if (threadIdx.x == 0) {
        float ts = ss[0], tm = sm[0];
        #pragma unroll
        for (int w = 1; w < 8; w++) { ts += ss[w]; tm = fmaxf(tm, sm[w]); }
        g_avgp[row] = ts * (1.0f / HW_);
        g_maxp[row] = tm;
    }
}

// ---------------------------------------------------------------------------
// K2: fused MLP + sigmoid + top-128 rank. One block per (n, d).
//   key = (bits(sigmoid)<<16) | (65535-c): sigmoid>0 -> monotone float bits;
//   low-bits index tiebreak = exact lax.top_k order.
// ---------------------------------------------------------------------------
__global__ __launch_bounds__(512) void mlp_rank_kernel(
    const float* __restrict__ W1, const float* __restrict__ b1,
    const float* __restrict__ W2, const float* __restrict__ b2) {
    const int b   = blockIdx.x;      // n*D + d
    const int n   = b >> 2;
    const int d   = b & 3;
    const int tid = threadIdx.x;
    const int w   = tid >> 5;        // warp 0..15
    const int j   = tid & 31;        // lane = hidden index

    __shared__ float avg_s[C_];
    __shared__ float max_s[C_];
    __shared__ float part_a[16 * HID_];
    __shared__ float part_m[16 * HID_];
    __shared__ float hs[HID_];
    __shared__ unsigned long long keys[C_];

    avg_s[tid] = g_avgp[n * C_ + tid];
    max_s[tid] = g_maxp[n * C_ + tid];
    __syncthreads();

    // Layer 1, coalesced: warp w handles channels c = w, w+16, ...; lane j
    // reads W1[c][j] (one 128B line per warp per c).
    {
        float sa = 0.0f, smx = 0.0f;
        #pragma unroll 8
        for (int c = w; c < C_; c += 16) {
            float w1 = W1[c * HID_ + j];
            sa  = fmaf(avg_s[c], w1, sa);
            smx = fmaf(max_s[c], w1, smx);
        }
        part_a[w * HID_ + j] = sa;
        part_m[w * HID_ + j] = smx;
    }
    __syncthreads();
    if (tid < HID_) {
        float sa = 0.0f, smx = 0.0f;
        #pragma unroll
        for (int ww = 0; ww < 16; ww++) {
            sa  += part_a[ww * HID_ + tid];
            smx += part_m[ww * HID_ + tid];
        }
        float bb = b1[tid];
        hs[tid] = fmaxf(sa + bb, 0.0f) + fmaxf(smx + bb, 0.0f);
    }
    __syncthreads();

    // Layer 2 + sigmoid + key: thread c computes output o = c*4 + d.
    {
        const int c = tid;
        const int o = c * D_ + d;
        float acc = 2.0f * b2[o];
        #pragma unroll
        for (int k = 0; k < HID_; k++)
            acc = fmaf(hs[k], W2[k * CD_ + o], acc);
        float v = 1.0f / (1.0f + expf(-acc));
        keys[c] = ((unsigned long long)__float_as_uint(v) << 16) |
                  (unsigned long long)(65535 - c);
    }
    __syncthreads();

    // Rank by count.
    {
        const unsigned long long myk = keys[tid];
        int rank = 0;
        const ulonglong2* k2 = reinterpret_cast<const ulonglong2*>(keys);
        #pragma unroll 8
        for (int i = 0; i < C_ / 2; i++) {
            ulonglong2 u = k2[i];
            rank += (u.x > myk) + (u.y > myk);
        }
        if (rank < BLK_)
            g_idx[n * C_ + d * BLK_ + rank] = tid;
    }
}

// ---------------------------------------------------------------------------
// K3: gather, REVERSED row order. Pool streamed x row-major, so L2 holds the
// tail (~last 15 samples); starting gather at sample 31 turns those reads
// into L2 hits. Streaming hints on both sides of the copy.
// ---------------------------------------------------------------------------
__global__ __launch_bounds__(256) void gather_kernel(
    const float* __restrict__ x, float* __restrict__ out) {
    const int row = (N_ * C_ - 1) - blockIdx.x;      // descending
    const int n   = row >> 9;
    const int c   = g_idx[row];
    const float4* src = reinterpret_cast<const float4*>(
        x + ((size_t)n * C_ + c) * HW_);
    float4* dst = reinterpret_cast<float4*>(out + (size_t)row * HW_);
    #pragma unroll 4
    for (int i = threadIdx.x; i < HW_ / 4; i += 256) {
        float4 v = __ldcs(src + i);
        __stcs(dst + i, v);
    }
}

extern "C" void kernel_launch(void* const* d_in, const int* in_sizes, int n_in,
                              void* d_out, int out_size) {
    const float* x  = (const float*)d_in[0];
    const float* W1 = (const float*)d_in[1];
    const float* b1 = (const float*)d_in[2];
    const float* W2 = (const float*)d_in[3];
    const float* b2 = (const float*)d_in[4];
    float* out = (float*)d_out;

    pool_kernel<<<N_ * C_, 256>>>(x);
    mlp_rank_kernel<<<N_ * D_, 512>>>(W1, b1, W2, b2);
    gather_kernel<<<N_ * C_, 256>>>(x, out);
}